// round 1
// baseline (speedup 1.0000x reference)
#include <cuda_runtime.h>
#include <cub/cub.cuh>

#define B_ 8
#define P_ 57744
#define C_ 81
#define N_ 20
#define ROWS_ (B_ * P_)
#define POS_TH 0.5f
#define NEG_TH 0.4f

// ---------------- scratch (static __device__, no allocation) ----------------
__device__ float              g_bt_ov[ROWS_];
__device__ int                g_bt_idx[ROWS_];
__device__ unsigned long long g_gt_best[B_ * N_];
__device__ unsigned long long g_keys[ROWS_];
__device__ unsigned long long g_keys_sorted[ROWS_];
__device__ signed char        g_conf[ROWS_];
__device__ int                g_num_pos;
__device__ float              g_sl1;
__device__ float              g_ce_sum;
__device__ int                g_keep;
__device__ unsigned char      g_cub_temp[32u << 20];  // 32 MB for cub radix sort

__device__ __forceinline__ float smooth_l1(float d) {
    float ad = fabsf(d);
    return ad < 1.f ? 0.5f * d * d : ad - 0.5f;
}

// ---------------- K0: per-replay state reset ----------------
__global__ void k_init() {
    int t = threadIdx.x;
    if (t == 0) { g_num_pos = 0; g_sl1 = 0.f; g_ce_sum = 0.f; g_keep = 0; }
    // key(iou=0, p=0) = (bits(0.0)<<32) | ~0u  -> argmax fallback = prior 0
    if (t < B_ * N_) g_gt_best[t] = 0x00000000FFFFFFFFull;
}

// ---------------- K1: matching (per-prior best GT + per-GT best prior) ------
__global__ void k_match(const float* __restrict__ priors,
                        const float* __restrict__ gt_boxes) {
    int b = blockIdx.y;
    int p = blockIdx.x * 256 + threadIdx.x;

    __shared__ float4 s_gt[N_];
    __shared__ float  s_area[N_];
    __shared__ unsigned long long s_best[N_];
    if (threadIdx.x < N_) {
        float4 g = reinterpret_cast<const float4*>(gt_boxes)[b * N_ + threadIdx.x];
        s_gt[threadIdx.x] = g;
        s_area[threadIdx.x] = (g.z - g.x) * (g.w - g.y);
        s_best[threadIdx.x] = 0ull;
    }
    __syncthreads();

    if (p < P_) {
        float4 pr = reinterpret_cast<const float4*>(priors)[p];
        float px1 = pr.x - pr.z * 0.5f, py1 = pr.y - pr.w * 0.5f;
        float px2 = pr.x + pr.z * 0.5f, py2 = pr.y + pr.w * 0.5f;
        float parea = (px2 - px1) * (py2 - py1);

        float best = 0.f; int bestn = 0;
        #pragma unroll
        for (int n = 0; n < N_; n++) {
            float4 g = s_gt[n];
            float ix1 = fmaxf(px1, g.x), iy1 = fmaxf(py1, g.y);
            float ix2 = fminf(px2, g.z), iy2 = fminf(py2, g.w);
            float iw = fmaxf(ix2 - ix1, 0.f), ih = fmaxf(iy2 - iy1, 0.f);
            float inter = iw * ih;
            float iou = inter / (s_area[n] + parea - inter);
            if (iou > best) { best = iou; bestn = n; }  // strict: lowest n on tie
            if (inter > 0.f) {
                // tie-break toward lowest p (matches jnp argmax)
                unsigned long long key =
                    (((unsigned long long)__float_as_uint(iou)) << 32) |
                    (unsigned)(~(unsigned)p);
                atomicMax(&s_best[n], key);
            }
        }
        g_bt_ov[b * P_ + p]  = best;
        g_bt_idx[b * P_ + p] = bestn;
    }
    __syncthreads();
    if (threadIdx.x < N_)
        atomicMax(&g_gt_best[b * N_ + threadIdx.x], s_best[threadIdx.x]);
}

// ---------------- K2: force-match (sequential per batch, last GT wins) ------
__global__ void k_force() {
    int b = threadIdx.x;
    if (b < B_) {
        for (int n = 0; n < N_; n++) {
            unsigned long long key = g_gt_best[b * N_ + n];
            unsigned p = ~(unsigned)(key & 0xFFFFFFFFull);
            g_bt_ov[b * P_ + p]  = 2.0f;
            g_bt_idx[b * P_ + p] = n;
        }
    }
}

// ---------------- K3: conf scan (150 MB read): conf_t, fg-score key, loc loss
__global__ void __launch_bounds__(256)
k_conf(const float* __restrict__ conf_data,
       const float* __restrict__ loc_data,
       const float* __restrict__ priors,
       const float* __restrict__ gt_boxes,
       const int* __restrict__ gt_labels) {
    const float NINF = __int_as_float(0xff800000);
    int lane = threadIdx.x & 31;
    int wid  = (blockIdx.x * blockDim.x + threadIdx.x) >> 5;
    int nw   = (gridDim.x * blockDim.x) >> 5;

    int   lnp = 0;
    float lsl = 0.f;

    for (int r = wid; r < ROWS_; r += nw) {
        const float* row = conf_data + (size_t)r * C_;
        float x0 = row[lane];
        float x1 = row[lane + 32];
        float x2 = (lane < 17) ? row[lane + 64] : NINF;
        // fg max: exclude class 0
        float f = fmaxf(lane == 0 ? NINF : x0, fmaxf(x1, x2));
        #pragma unroll
        for (int o = 16; o; o >>= 1) f = fmaxf(f, __shfl_xor_sync(0xffffffffu, f, o));

        if (lane == 0) {
            float ov = g_bt_ov[r];
            int   n  = g_bt_idx[r];
            int   b  = r / P_;
            int   c  = (ov < NEG_TH) ? 0 : ((ov < POS_TH) ? -1 : gt_labels[b * N_ + n]);
            g_conf[r] = (signed char)c;

            unsigned u = 0;  // non-candidates sort below every candidate
            if (c == 0) {
                unsigned fb = __float_as_uint(f);
                u = (fb & 0x80000000u) ? ~fb : (fb | 0x80000000u);
            }
            // stable tie-break: lower row index ranks first under descending sort
            g_keys[r] = (((unsigned long long)u) << 32) | (unsigned)(~(unsigned)r);

            if (c > 0) {
                lnp++;
                int p = r - b * P_;
                float4 pr = reinterpret_cast<const float4*>(priors)[p];
                float4 g  = reinterpret_cast<const float4*>(gt_boxes)[b * N_ + n];
                float4 ld = reinterpret_cast<const float4*>(loc_data)[r];
                float tx = ((g.x + g.z) * 0.5f - pr.x) / (0.1f * pr.z);
                float ty = ((g.y + g.w) * 0.5f - pr.y) / (0.1f * pr.w);
                float tw = logf((g.z - g.x) / pr.z) * 5.0f;
                float th = logf((g.w - g.y) / pr.w) * 5.0f;
                lsl += smooth_l1(ld.x - tx) + smooth_l1(ld.y - ty)
                     + smooth_l1(ld.z - tw) + smooth_l1(ld.w - th);
            }
        }
    }

    __shared__ float sf[8];
    __shared__ int   si[8];
    int w = threadIdx.x >> 5;
    if (lane == 0) { sf[w] = lsl; si[w] = lnp; }
    __syncthreads();
    if (threadIdx.x == 0) {
        float a = 0.f; int ni = 0;
        #pragma unroll
        for (int i = 0; i < 8; i++) { a += sf[i]; ni += si[i]; }
        if (ni)       atomicAdd(&g_num_pos, ni);
        if (a != 0.f) atomicAdd(&g_sl1, a);
    }
}

// ---------------- K5: selection + CE only on kept rows ----------------------
__global__ void __launch_bounds__(256)
k_final(const float* __restrict__ conf_data) {
    const float NINF = __int_as_float(0xff800000);
    int np = g_num_pos;
    long long K = 3LL * np;
    if (K > ROWS_) K = ROWS_;
    unsigned long long tkey = (K > 0) ? g_keys_sorted[K - 1] : ~0ull;

    int lane = threadIdx.x & 31;
    int wid  = (blockIdx.x * blockDim.x + threadIdx.x) >> 5;
    int nw   = (gridDim.x * blockDim.x) >> 5;

    float lce = 0.f;
    int   lkp = 0;

    for (int r = wid; r < ROWS_; r += nw) {
        int keep = 0, c = 0;
        if (lane == 0) {
            c = g_conf[r];
            keep = (c > 0) || (c == 0 && K > 0 && g_keys[r] >= tkey);
        }
        keep = __shfl_sync(0xffffffffu, keep, 0);
        if (keep) {
            c = __shfl_sync(0xffffffffu, c, 0);
            const float* row = conf_data + (size_t)r * C_;
            float x0 = row[lane];
            float x1 = row[lane + 32];
            float x2 = (lane < 17) ? row[lane + 64] : NINF;
            float m = fmaxf(x0, fmaxf(x1, x2));
            #pragma unroll
            for (int o = 16; o; o >>= 1) m = fmaxf(m, __shfl_xor_sync(0xffffffffu, m, o));
            float s = expf(x0 - m) + expf(x1 - m) + ((lane < 17) ? expf(x2 - m) : 0.f);
            #pragma unroll
            for (int o = 16; o; o >>= 1) s += __shfl_xor_sync(0xffffffffu, s, o);

            int ct = c > 0 ? c : 0;  // clip(-1 -> 0); keep=false rows never get here with c=-1
            float tv = NINF;
            if (lane == ct)                  tv = x0;
            if (lane + 32 == ct)             tv = x1;
            if (lane < 17 && lane + 64 == ct) tv = x2;
            #pragma unroll
            for (int o = 16; o; o >>= 1) tv = fmaxf(tv, __shfl_xor_sync(0xffffffffu, tv, o));

            if (lane == 0) { lce += (m + logf(s)) - tv; lkp++; }
        }
    }

    __shared__ float sf[8];
    __shared__ int   si[8];
    int w = threadIdx.x >> 5;
    if (lane == 0) { sf[w] = lce; si[w] = lkp; }
    __syncthreads();
    if (threadIdx.x == 0) {
        float a = 0.f; int k = 0;
        #pragma unroll
        for (int i = 0; i < 8; i++) { a += sf[i]; k += si[i]; }
        if (k)        atomicAdd(&g_keep, k);
        if (a != 0.f) atomicAdd(&g_ce_sum, a);
    }
}

// ---------------- K6: finalize ----------------------------------------------
__global__ void k_out(float* __restrict__ out) {
    int np = g_num_pos; if (np < 1) np = 1;
    int kp = g_keep;    if (kp < 1) kp = 1;
    out[0] = g_sl1    / (float)np;
    out[1] = g_ce_sum / (float)kp;
}

// ---------------- host -------------------------------------------------------
extern "C" void kernel_launch(void* const* d_in, const int* in_sizes, int n_in,
                              void* d_out, int out_size) {
    const float* loc = nullptr;
    const float* conf = nullptr;
    const float* priors = nullptr;
    const float* gtb = nullptr;
    const int*   gtl = nullptr;
    for (int i = 0; i < n_in; i++) {
        long long s = in_sizes[i];
        if      (s == (long long)B_ * P_ * C_) conf   = (const float*)d_in[i];
        else if (s == (long long)B_ * P_ * 4)  loc    = (const float*)d_in[i];
        else if (s == (long long)P_ * 4)       priors = (const float*)d_in[i];
        else if (s == (long long)B_ * N_ * 4)  gtb    = (const float*)d_in[i];
        else if (s == (long long)B_ * N_)      gtl    = (const int*)d_in[i];
    }
    float* out = (float*)d_out;

    k_init<<<1, 256>>>();
    k_match<<<dim3((P_ + 255) / 256, B_), 256>>>(priors, gtb);
    k_force<<<1, 32>>>();
    k_conf<<<1776, 256>>>(conf, loc, priors, gtb, gtl);

    // stable descending sort of (score, ~row) keys via CUB (graph-capturable)
    void *d_keys = nullptr, *d_keys_out = nullptr, *d_temp = nullptr;
    cudaGetSymbolAddress(&d_keys, g_keys);
    cudaGetSymbolAddress(&d_keys_out, g_keys_sorted);
    cudaGetSymbolAddress(&d_temp, g_cub_temp);
    size_t temp_bytes = 0;
    cub::DeviceRadixSort::SortKeysDescending(
        nullptr, temp_bytes,
        (const unsigned long long*)d_keys, (unsigned long long*)d_keys_out,
        ROWS_, 0, 64, (cudaStream_t)0);
    if (temp_bytes <= sizeof(g_cub_temp)) {
        cub::DeviceRadixSort::SortKeysDescending(
            d_temp, temp_bytes,
            (const unsigned long long*)d_keys, (unsigned long long*)d_keys_out,
            ROWS_, 0, 64, (cudaStream_t)0);
    }

    k_final<<<1776, 256>>>(conf);
    k_out<<<1, 1>>>(out);
}

// round 2
// speedup vs baseline: 1.4289x; 1.4289x over previous
#include <cuda_runtime.h>

#define B_ 8
#define P_ 57744
#define C_ 81
#define N_ 20
#define ROWS_ (B_ * P_)
#define POS_TH 0.5f
#define NEG_TH 0.4f
#define CAND_CAP 8192

// ---------------- scratch (static __device__, no allocation) ----------------
__device__ float              g_bt_ov[ROWS_];
__device__ int                g_bt_idx[ROWS_];
__device__ unsigned long long g_gt_best[B_ * N_];
__device__ unsigned long long g_keys[ROWS_];
__device__ signed char        g_conf[ROWS_];
__device__ int                g_hist[3][2048];
__device__ unsigned long long g_cand[CAND_CAP];
__device__ int                g_cand_cnt;
__device__ unsigned long long g_pref;     // running digit prefix of the select
__device__ long long          g_Krem;     // remaining rank within current bucket
__device__ int                g_K;        // total K = min(3*num_pos, ROWS)
__device__ unsigned long long g_tkey;     // exact K-th largest key
__device__ int                g_work[ROWS_];
__device__ int                g_work_cnt;
__device__ int                g_num_pos;
__device__ float              g_sl1;
__device__ float              g_ce_sum;

__device__ __forceinline__ float smooth_l1(float d) {
    float ad = fabsf(d);
    return ad < 1.f ? 0.5f * d * d : ad - 0.5f;
}
__device__ __forceinline__ unsigned ord_bits(float x) {
    unsigned b = __float_as_uint(x);
    unsigned m = (unsigned)((int)b >> 31) | 0x80000000u;
    return b ^ m;   // monotonic: a<b (float) <=> ord(a)<ord(b) (uint)
}

// ---------------- K0: per-replay state reset ----------------
__global__ void k_init() {
    int t = threadIdx.x;
    if (t == 0) {
        g_num_pos = 0; g_sl1 = 0.f; g_ce_sum = 0.f;
        g_work_cnt = 0; g_cand_cnt = 0;
    }
    for (int i = t; i < 3 * 2048; i += blockDim.x)
        (&g_hist[0][0])[i] = 0;
    if (t < B_ * N_) g_gt_best[t] = 0x00000000FFFFFFFFull;  // fallback prior 0
}

// ---------------- K1: matching ----------------------------------------------
__global__ void k_match(const float* __restrict__ priors,
                        const float* __restrict__ gt_boxes) {
    int b = blockIdx.y;
    int p = blockIdx.x * 256 + threadIdx.x;

    __shared__ float4 s_gt[N_];
    __shared__ float  s_area[N_];
    __shared__ unsigned long long s_best[N_];
    if (threadIdx.x < N_) {
        float4 g = reinterpret_cast<const float4*>(gt_boxes)[b * N_ + threadIdx.x];
        s_gt[threadIdx.x] = g;
        s_area[threadIdx.x] = (g.z - g.x) * (g.w - g.y);
        s_best[threadIdx.x] = 0ull;
    }
    __syncthreads();

    if (p < P_) {
        float4 pr = reinterpret_cast<const float4*>(priors)[p];
        float px1 = pr.x - pr.z * 0.5f, py1 = pr.y - pr.w * 0.5f;
        float px2 = pr.x + pr.z * 0.5f, py2 = pr.y + pr.w * 0.5f;
        float parea = (px2 - px1) * (py2 - py1);

        float best = 0.f; int bestn = 0;
        #pragma unroll
        for (int n = 0; n < N_; n++) {
            float4 g = s_gt[n];
            float ix1 = fmaxf(px1, g.x), iy1 = fmaxf(py1, g.y);
            float ix2 = fminf(px2, g.z), iy2 = fminf(py2, g.w);
            float iw = fmaxf(ix2 - ix1, 0.f), ih = fmaxf(iy2 - iy1, 0.f);
            float inter = iw * ih;
            float iou = inter / (s_area[n] + parea - inter);
            if (iou > best) { best = iou; bestn = n; }
            if (inter > 0.f) {
                unsigned long long key =
                    (((unsigned long long)__float_as_uint(iou)) << 32) |
                    (unsigned)(~(unsigned)p);
                atomicMax(&s_best[n], key);
            }
        }
        g_bt_ov[b * P_ + p]  = best;
        g_bt_idx[b * P_ + p] = bestn;
    }
    __syncthreads();
    if (threadIdx.x < N_)
        atomicMax(&g_gt_best[b * N_ + threadIdx.x], s_best[threadIdx.x]);
}

// ---------------- K2: force-match (sequential per batch, last GT wins) ------
__global__ void k_force() {
    int b = threadIdx.x;
    if (b < B_) {
        for (int n = 0; n < N_; n++) {
            unsigned long long key = g_gt_best[b * N_ + n];
            unsigned p = ~(unsigned)(key & 0xFFFFFFFFull);
            g_bt_ov[b * P_ + p]  = 2.0f;
            g_bt_idx[b * P_ + p] = n;
        }
    }
}

// ---------------- K3: conf scan + keys + loc loss + round-1 hist -------------
__global__ void __launch_bounds__(256)
k_conf(const float* __restrict__ conf_data,
       const float* __restrict__ loc_data,
       const float* __restrict__ priors,
       const float* __restrict__ gt_boxes,
       const int* __restrict__ gt_labels) {
    __shared__ int s_hist[2048];
    for (int i = threadIdx.x; i < 2048; i += 256) s_hist[i] = 0;
    __syncthreads();

    const int lane = threadIdx.x & 31;
    const int wid  = (blockIdx.x * blockDim.x + threadIdx.x) >> 5;
    const int nw   = (gridDim.x * blockDim.x) >> 5;

    float lsl = 0.f;
    int   lnp = 0;
    const int NCH = ROWS_ / 4;

    for (int ch = wid; ch < NCH; ch += nw) {
        int r0 = ch * 4;
        unsigned uu0, uu1, uu2, uu3;
        #pragma unroll
        for (int j = 0; j < 4; j++) {
            const float* row = conf_data + (size_t)(r0 + j) * C_;
            float x0 = row[lane];
            float x1 = row[lane + 32];
            float x2 = (lane < 17) ? row[lane + 64] : 0.f;
            unsigned o0 = lane ? ord_bits(x0) : 0u;       // exclude class 0
            unsigned o1 = ord_bits(x1);
            unsigned o2 = (lane < 17) ? ord_bits(x2) : 0u;
            unsigned u = max(max(o0, o1), o2);
            unsigned m = __reduce_max_sync(0xffffffffu, u);
            if (j == 0) uu0 = m; else if (j == 1) uu1 = m;
            else if (j == 2) uu2 = m; else uu3 = m;
        }
        if (lane < 4) {
            int r = r0 + lane;
            unsigned uu = lane == 0 ? uu0 : lane == 1 ? uu1 : lane == 2 ? uu2 : uu3;
            float ov = g_bt_ov[r];
            int   n  = g_bt_idx[r];
            int   b  = r / P_;
            int   c  = (ov < NEG_TH) ? 0 : ((ov < POS_TH) ? -1 : gt_labels[b * N_ + n]);
            g_conf[r] = (signed char)c;
            unsigned u = (c == 0) ? uu : 0u;
            unsigned long long key =
                (((unsigned long long)u) << 32) | (unsigned)(~(unsigned)r);
            g_keys[r] = key;
            atomicAdd(&s_hist[(int)(key >> 53)], 1);
            if (c > 0) {
                lnp++;
                int p = r - b * P_;
                float4 pr = reinterpret_cast<const float4*>(priors)[p];
                float4 g  = reinterpret_cast<const float4*>(gt_boxes)[b * N_ + n];
                float4 ld = reinterpret_cast<const float4*>(loc_data)[r];
                float tx = ((g.x + g.z) * 0.5f - pr.x) / (0.1f * pr.z);
                float ty = ((g.y + g.w) * 0.5f - pr.y) / (0.1f * pr.w);
                float tw = logf((g.z - g.x) / pr.z) * 5.0f;
                float th = logf((g.w - g.y) / pr.w) * 5.0f;
                lsl += smooth_l1(ld.x - tx) + smooth_l1(ld.y - ty)
                     + smooth_l1(ld.z - tw) + smooth_l1(ld.w - th);
            }
        }
    }

    #pragma unroll
    for (int o = 16; o; o >>= 1) {
        lsl += __shfl_xor_sync(0xffffffffu, lsl, o);
        lnp += __shfl_xor_sync(0xffffffffu, lnp, o);
    }
    __shared__ float sf[8];
    __shared__ int   si[8];
    int w = threadIdx.x >> 5;
    if (lane == 0) { sf[w] = lsl; si[w] = lnp; }
    __syncthreads();
    if (threadIdx.x == 0) {
        float a = 0.f; int ni = 0;
        #pragma unroll
        for (int i = 0; i < 8; i++) { a += sf[i]; ni += si[i]; }
        if (ni)       atomicAdd(&g_num_pos, ni);
        if (a != 0.f) atomicAdd(&g_sl1, a);
    }
    for (int i = threadIdx.x; i < 2048; i += 256) {
        int v = s_hist[i];
        if (v) atomicAdd(&g_hist[0][i], v);
    }
}

// ---------------- radix-select: pick 11-bit digit from a histogram ----------
__global__ void k_select(int histIdx, int first) {
    __shared__ long long partial[256];
    __shared__ long long sKrem;
    __shared__ int sK;
    if (threadIdx.x == 0) {
        if (first) {
            long long K = 3LL * g_num_pos;
            if (K > ROWS_) K = ROWS_;
            g_K = (int)K; g_Krem = K; g_pref = 0;
            if (K == 0) g_tkey = ~0ull;
        }
        sKrem = g_Krem; sK = g_K;
    }
    __syncthreads();
    if (sK == 0) return;
    int t = threadIdx.x;
    long long s = 0;
    #pragma unroll
    for (int i = 0; i < 8; i++) s += g_hist[histIdx][t * 8 + i];
    partial[t] = s;
    __syncthreads();
    if (t == 0) {
        long long Krem = sKrem, above = 0;
        int seg = 255;
        for (; seg > 0; seg--) {
            if (above + partial[seg] >= Krem) break;
            above += partial[seg];
        }
        int d = seg * 8;
        for (int i = 7; i >= 0; i--) {
            int cgt = g_hist[histIdx][seg * 8 + i];
            if (above + cgt >= Krem) { d = seg * 8 + i; break; }
            above += cgt;
        }
        g_pref = (g_pref << 11) | (unsigned)d;
        g_Krem = Krem - above;
    }
}

// ---------------- radix-select: histogram next 11-bit digit under prefix ----
__global__ void __launch_bounds__(256)
k_hist(int histIdx, int shift, int prefShift) {
    __shared__ int sh[2048];
    for (int i = threadIdx.x; i < 2048; i += 256) sh[i] = 0;
    __syncthreads();
    if (g_K == 0) return;
    unsigned long long pref = g_pref;
    int t = blockIdx.x * 256 + threadIdx.x;
    int stride = gridDim.x * 256;
    for (int r = t; r < ROWS_; r += stride) {
        unsigned long long key = g_keys[r];
        if ((key >> prefShift) == pref)
            atomicAdd(&sh[(int)((key >> shift) & 2047)], 1);
    }
    __syncthreads();
    for (int i = threadIdx.x; i < 2048; i += 256) {
        int v = sh[i];
        if (v) atomicAdd(&g_hist[histIdx][i], v);
    }
}

// ---------------- collect 33-bit-prefix tie set ------------------------------
__global__ void k_collect() {
    if (g_K == 0) return;
    unsigned long long pref = g_pref;  // 33 bits
    int t = blockIdx.x * 256 + threadIdx.x;
    int stride = gridDim.x * 256;
    for (int r = t; r < ROWS_; r += stride) {
        unsigned long long key = g_keys[r];
        if ((key >> 31) == pref) {
            int pos = atomicAdd(&g_cand_cnt, 1);
            if (pos < CAND_CAP) g_cand[pos] = key;
        }
    }
}

// ---------------- exact final threshold over remaining 31 bits ---------------
__global__ void __launch_bounds__(256) k_finalsel() {
    __shared__ unsigned sm[CAND_CAP];
    __shared__ int scnt;
    if (g_K == 0) return;  // tkey already ~0
    int cnt = g_cand_cnt;
    if (cnt > CAND_CAP) cnt = CAND_CAP;
    for (int i = threadIdx.x; i < cnt; i += 256)
        sm[i] = (unsigned)(g_cand[i] & 0x7FFFFFFFull);
    __syncthreads();
    long long Krem = g_Krem;
    unsigned P = 0;
    for (int b = 30; b >= 0; b--) {
        if (threadIdx.x == 0) scnt = 0;
        __syncthreads();
        int local = 0;
        for (int i = threadIdx.x; i < cnt; i += 256) {
            unsigned m = sm[i];
            if ((m >> (b + 1)) == P && ((m >> b) & 1u)) local++;
        }
        if (local) atomicAdd(&scnt, local);
        __syncthreads();
        long long c1 = scnt;
        if (c1 >= Krem) P = (P << 1) | 1u;
        else { Krem -= c1; P <<= 1; }
        __syncthreads();
    }
    if (threadIdx.x == 0) g_tkey = (g_pref << 31) | P;
}

// ---------------- keep filter -> compact worklist ----------------------------
__global__ void __launch_bounds__(256) k_keep() {
    int K = g_K;
    unsigned long long tkey = g_tkey;
    int t = blockIdx.x * 256 + threadIdx.x;
    int stride = gridDim.x * 256;
    for (int r = t; r < ROWS_; r += stride) {
        int c = g_conf[r];
        bool keep = (c > 0) || (c == 0 && K > 0 && g_keys[r] >= tkey);
        unsigned bal = __ballot_sync(0xffffffffu, keep);
        if (bal) {
            int cnt = __popc(bal);
            int base = 0;
            if ((threadIdx.x & 31) == 0) base = atomicAdd(&g_work_cnt, cnt);
            base = __shfl_sync(0xffffffffu, base, 0);
            if (keep) {
                int idx = base + __popc(bal & ((1u << (threadIdx.x & 31)) - 1u));
                g_work[idx] = (r << 8) | (c > 0 ? c : 0);
            }
        }
    }
}

// ---------------- CE only on kept rows ---------------------------------------
__global__ void __launch_bounds__(256) k_ce(const float* __restrict__ conf_data) {
    const float NINF = __int_as_float(0xff800000);
    int lane = threadIdx.x & 31;
    int wid  = (blockIdx.x * blockDim.x + threadIdx.x) >> 5;
    int nw   = (gridDim.x * blockDim.x) >> 5;
    int cnt = g_work_cnt;
    float lce = 0.f;

    for (int i = wid; i < cnt; i += nw) {
        int item = g_work[i];
        int r  = item >> 8;
        int ct = item & 255;
        const float* row = conf_data + (size_t)r * C_;
        float x0 = row[lane];
        float x1 = row[lane + 32];
        float x2 = (lane < 17) ? row[lane + 64] : NINF;
        float m = fmaxf(x0, fmaxf(x1, x2));
        #pragma unroll
        for (int o = 16; o; o >>= 1) m = fmaxf(m, __shfl_xor_sync(0xffffffffu, m, o));
        float s = expf(x0 - m) + expf(x1 - m) + ((lane < 17) ? expf(x2 - m) : 0.f);
        #pragma unroll
        for (int o = 16; o; o >>= 1) s += __shfl_xor_sync(0xffffffffu, s, o);
        float tv = NINF;
        if (lane == ct)                   tv = x0;
        if (lane + 32 == ct)              tv = x1;
        if (lane < 17 && lane + 64 == ct) tv = x2;
        #pragma unroll
        for (int o = 16; o; o >>= 1) tv = fmaxf(tv, __shfl_xor_sync(0xffffffffu, tv, o));
        if (lane == 0) lce += (m + logf(s)) - tv;
    }

    #pragma unroll
    for (int o = 16; o; o >>= 1) lce += __shfl_xor_sync(0xffffffffu, lce, o);
    __shared__ float sf[8];
    int w = threadIdx.x >> 5;
    if (lane == 0) sf[w] = lce;
    __syncthreads();
    if (threadIdx.x == 0) {
        float a = 0.f;
        #pragma unroll
        for (int i = 0; i < 8; i++) a += sf[i];
        if (a != 0.f) atomicAdd(&g_ce_sum, a);
    }
}

// ---------------- finalize ---------------------------------------------------
__global__ void k_out(float* __restrict__ out) {
    int np = g_num_pos;  if (np < 1) np = 1;
    int kp = g_work_cnt; if (kp < 1) kp = 1;
    out[0] = g_sl1    / (float)np;
    out[1] = g_ce_sum / (float)kp;
}

// ---------------- host -------------------------------------------------------
extern "C" void kernel_launch(void* const* d_in, const int* in_sizes, int n_in,
                              void* d_out, int out_size) {
    const float* loc = nullptr;
    const float* conf = nullptr;
    const float* priors = nullptr;
    const float* gtb = nullptr;
    const int*   gtl = nullptr;
    for (int i = 0; i < n_in; i++) {
        long long s = in_sizes[i];
        if      (s == (long long)B_ * P_ * C_) conf   = (const float*)d_in[i];
        else if (s == (long long)B_ * P_ * 4)  loc    = (const float*)d_in[i];
        else if (s == (long long)P_ * 4)       priors = (const float*)d_in[i];
        else if (s == (long long)B_ * N_ * 4)  gtb    = (const float*)d_in[i];
        else if (s == (long long)B_ * N_)      gtl    = (const int*)d_in[i];
    }
    float* out = (float*)d_out;

    k_init<<<1, 1024>>>();
    k_match<<<dim3((P_ + 255) / 256, B_), 256>>>(priors, gtb);
    k_force<<<1, 32>>>();
    k_conf<<<1776, 256>>>(conf, loc, priors, gtb, gtl);   // + round-1 hist

    k_select<<<1, 256>>>(0, 1);                 // digit 1 (bits 63:53), sets K
    k_hist<<<296, 256>>>(1, 42, 53);            // round-2 hist
    k_select<<<1, 256>>>(1, 0);                 // digit 2 (bits 52:42)
    k_hist<<<296, 256>>>(2, 31, 42);            // round-3 hist
    k_select<<<1, 256>>>(2, 0);                 // digit 3 (bits 41:31)
    k_collect<<<296, 256>>>();                  // gather 33-bit-prefix ties
    k_finalsel<<<1, 256>>>();                   // exact low-31-bit resolve

    k_keep<<<1805, 256>>>();
    k_ce<<<232, 256>>>(conf);
    k_out<<<1, 1>>>(out);
}

// round 3
// speedup vs baseline: 1.7966x; 1.2573x over previous
#include <cuda_runtime.h>

#define B_ 8
#define P_ 57744
#define C_ 81
#define N_ 20
#define ROWS_ (B_ * P_)
#define POS_TH 0.5f
#define NEG_TH 0.4f
#define CAND_CAP 65536

// ---------------- scratch (static __device__, no allocation) ----------------
__device__ float              g_bt_ov[ROWS_];
__device__ int                g_bt_idx[ROWS_];
__device__ unsigned long long g_gt_best[B_ * N_];
__device__ unsigned long long g_keys[ROWS_];
__device__ signed char        g_conf[ROWS_];
__device__ int                g_hist[2][2048];
__device__ unsigned long long g_cand[CAND_CAP];
__device__ int                g_cand_cnt;
__device__ unsigned long long g_tkey;
__device__ int                g_num_pos;
__device__ int                g_keep;
__device__ float              g_sl1;
__device__ float              g_ce_sum;
__device__ int                g_done;

__device__ __forceinline__ float smooth_l1(float d) {
    float ad = fabsf(d);
    return ad < 1.f ? 0.5f * d * d : ad - 0.5f;
}
__device__ __forceinline__ unsigned ord_bits(float x) {
    unsigned b = __float_as_uint(x);
    unsigned m = (unsigned)((int)b >> 31) | 0x80000000u;
    return b ^ m;   // monotonic float -> uint
}

// block-cooperative: digit of the Krem-th largest key in an 11-bit histogram.
// Returns digit; Krem updated to rank within that digit bucket. 256 threads.
__device__ int pick_digit(const int* hist, long long Krem_in, long long& Krem_out) {
    __shared__ long long part[256];
    __shared__ int s_d;
    __shared__ long long s_krem;
    int t = threadIdx.x;
    long long s = 0;
    #pragma unroll
    for (int i = 0; i < 8; i++) s += hist[t * 8 + i];
    part[t] = s;
    __syncthreads();
    if (t == 0) {
        long long above = 0;
        int seg = 255;
        for (; seg > 0; seg--) {
            if (above + part[seg] >= Krem_in) break;
            above += part[seg];
        }
        int d = seg * 8;
        for (int i = 7; i >= 0; i--) {
            int cgt = hist[seg * 8 + i];
            if (above + cgt >= Krem_in) { d = seg * 8 + i; break; }
            above += cgt;
        }
        s_d = d;
        s_krem = Krem_in - above;
    }
    __syncthreads();
    Krem_out = s_krem;
    return s_d;
}

// ---------------- K0: per-replay reset ---------------------------------------
__global__ void k_init() {
    int t = threadIdx.x;
    if (t == 0) {
        g_num_pos = 0; g_sl1 = 0.f; g_ce_sum = 0.f;
        g_keep = 0; g_cand_cnt = 0; g_done = 0;
    }
    for (int i = t; i < 2 * 2048; i += blockDim.x) (&g_hist[0][0])[i] = 0;
    if (t < B_ * N_) g_gt_best[t] = 0x00000000FFFFFFFFull;  // fallback prior 0
}

// ---------------- K1: matching ----------------------------------------------
__global__ void k_match(const float* __restrict__ priors,
                        const float* __restrict__ gt_boxes) {
    int b = blockIdx.y;
    int p = blockIdx.x * 256 + threadIdx.x;

    __shared__ float4 s_gt[N_];
    __shared__ float  s_area[N_];
    __shared__ unsigned long long s_best[N_];
    if (threadIdx.x < N_) {
        float4 g = reinterpret_cast<const float4*>(gt_boxes)[b * N_ + threadIdx.x];
        s_gt[threadIdx.x] = g;
        s_area[threadIdx.x] = (g.z - g.x) * (g.w - g.y);
        s_best[threadIdx.x] = 0ull;
    }
    __syncthreads();

    if (p < P_) {
        float4 pr = reinterpret_cast<const float4*>(priors)[p];
        float px1 = pr.x - pr.z * 0.5f, py1 = pr.y - pr.w * 0.5f;
        float px2 = pr.x + pr.z * 0.5f, py2 = pr.y + pr.w * 0.5f;
        float parea = (px2 - px1) * (py2 - py1);

        float best = 0.f; int bestn = 0;
        #pragma unroll
        for (int n = 0; n < N_; n++) {
            float4 g = s_gt[n];
            float ix1 = fmaxf(px1, g.x), iy1 = fmaxf(py1, g.y);
            float ix2 = fminf(px2, g.z), iy2 = fminf(py2, g.w);
            float iw = fmaxf(ix2 - ix1, 0.f), ih = fmaxf(iy2 - iy1, 0.f);
            float inter = iw * ih;
            float iou = inter / (s_area[n] + parea - inter);
            if (iou > best) { best = iou; bestn = n; }
            if (inter > 0.f) {
                unsigned long long key =
                    (((unsigned long long)__float_as_uint(iou)) << 32) |
                    (unsigned)(~(unsigned)p);
                atomicMax(&s_best[n], key);
            }
        }
        g_bt_ov[b * P_ + p]  = best;
        g_bt_idx[b * P_ + p] = bestn;
    }
    __syncthreads();
    if (threadIdx.x < N_)
        atomicMax(&g_gt_best[b * N_ + threadIdx.x], s_best[threadIdx.x]);
}

// ---------------- K2: conf scan (8 rows/warp-iter) + force-match + loc loss --
__global__ void __launch_bounds__(256)
k_conf(const float* __restrict__ conf_data,
       const float* __restrict__ loc_data,
       const float* __restrict__ priors,
       const float* __restrict__ gt_boxes,
       const int* __restrict__ gt_labels) {
    __shared__ int s_hist[2048];
    __shared__ int s_forced[B_ * N_];
    for (int i = threadIdx.x; i < 2048; i += 256) s_hist[i] = 0;
    if (threadIdx.x < B_ * N_)
        s_forced[threadIdx.x] =
            (int)(~(unsigned)(g_gt_best[threadIdx.x] & 0xFFFFFFFFull));
    __syncthreads();

    const int lane = threadIdx.x & 31;
    const int wid  = (blockIdx.x * blockDim.x + threadIdx.x) >> 5;
    const int nw   = (gridDim.x * blockDim.x) >> 5;

    float lsl = 0.f;
    int   lnp = 0;
    const int NCH = ROWS_ / 8;

    for (int ch = wid; ch < NCH; ch += nw) {
        int r0 = ch * 8;
        const float* base = conf_data + (size_t)r0 * C_;
        float xa[8], xb[8], xc[8];
        #pragma unroll
        for (int j = 0; j < 8; j++) {
            const float* row = base + j * C_;
            xa[j] = row[lane];
            xb[j] = row[lane + 32];
            xc[j] = (lane < 17) ? row[lane + 64] : 0.f;
        }
        unsigned mr[8];
        #pragma unroll
        for (int j = 0; j < 8; j++) {
            unsigned u = max(max(lane ? ord_bits(xa[j]) : 0u, ord_bits(xb[j])),
                             (lane < 17) ? ord_bits(xc[j]) : 0u);
            mr[j] = __reduce_max_sync(0xffffffffu, u);
        }
        if (lane < 8) {
            unsigned uu = (lane & 4)
                ? ((lane & 2) ? ((lane & 1) ? mr[7] : mr[6])
                              : ((lane & 1) ? mr[5] : mr[4]))
                : ((lane & 2) ? ((lane & 1) ? mr[3] : mr[2])
                              : ((lane & 1) ? mr[1] : mr[0]));
            int r = r0 + lane;
            int b = r / P_;
            int p = r - b * P_;
            float ov = g_bt_ov[r];
            int   n  = g_bt_idx[r];
            #pragma unroll
            for (int n2 = 0; n2 < N_; n2++)
                if (s_forced[b * N_ + n2] == p) { ov = 2.0f; n = n2; }
            int c = (ov < NEG_TH) ? 0 : ((ov < POS_TH) ? -1 : gt_labels[b * N_ + n]);
            g_conf[r] = (signed char)c;
            unsigned u = (c == 0) ? uu : 0u;
            unsigned long long key =
                (((unsigned long long)u) << 32) | (unsigned)(~(unsigned)r);
            g_keys[r] = key;
            atomicAdd(&s_hist[(int)(key >> 53)], 1);
            if (c > 0) {
                lnp++;
                float4 pr = reinterpret_cast<const float4*>(priors)[p];
                float4 g  = reinterpret_cast<const float4*>(gt_boxes)[b * N_ + n];
                float4 ld = reinterpret_cast<const float4*>(loc_data)[r];
                float tx = ((g.x + g.z) * 0.5f - pr.x) / (0.1f * pr.z);
                float ty = ((g.y + g.w) * 0.5f - pr.y) / (0.1f * pr.w);
                float tw = logf((g.z - g.x) / pr.z) * 5.0f;
                float th = logf((g.w - g.y) / pr.w) * 5.0f;
                lsl += smooth_l1(ld.x - tx) + smooth_l1(ld.y - ty)
                     + smooth_l1(ld.z - tw) + smooth_l1(ld.w - th);
            }
        }
    }

    #pragma unroll
    for (int o = 16; o; o >>= 1) {
        lsl += __shfl_xor_sync(0xffffffffu, lsl, o);
        lnp += __shfl_xor_sync(0xffffffffu, lnp, o);
    }
    __shared__ float sf[8];
    __shared__ int   si[8];
    int w = threadIdx.x >> 5;
    if (lane == 0) { sf[w] = lsl; si[w] = lnp; }
    __syncthreads();
    if (threadIdx.x == 0) {
        float a = 0.f; int ni = 0;
        #pragma unroll
        for (int i = 0; i < 8; i++) { a += sf[i]; ni += si[i]; }
        if (ni)       atomicAdd(&g_num_pos, ni);
        if (a != 0.f) atomicAdd(&g_sl1, a);
    }
    __syncthreads();
    for (int i = threadIdx.x; i < 2048; i += 256) {
        int v = s_hist[i];
        if (v) atomicAdd(&g_hist[0][i], v);
    }
}

// ---------------- K3: round-2 histogram (digit1 recomputed per block) --------
__global__ void __launch_bounds__(256) k_hist2() {
    long long K = 3LL * g_num_pos;
    if (K > ROWS_) K = ROWS_;
    if (K == 0) return;
    long long Krem;
    int d1 = pick_digit(g_hist[0], K, Krem);
    unsigned long long pref = (unsigned long long)d1;

    __shared__ int sh[2048];
    for (int i = threadIdx.x; i < 2048; i += 256) sh[i] = 0;
    __syncthreads();
    int t = blockIdx.x * 256 + threadIdx.x;
    int stride = gridDim.x * 256;
    for (int r = t; r < ROWS_; r += stride) {
        unsigned long long key = g_keys[r];
        if ((key >> 53) == pref)
            atomicAdd(&sh[(int)((key >> 42) & 2047)], 1);
    }
    __syncthreads();
    for (int i = threadIdx.x; i < 2048; i += 256) {
        int v = sh[i];
        if (v) atomicAdd(&g_hist[1][i], v);
    }
}

// ---------------- K4: collect 22-bit-prefix ties -----------------------------
__global__ void __launch_bounds__(256) k_collect() {
    long long K = 3LL * g_num_pos;
    if (K > ROWS_) K = ROWS_;
    if (K == 0) return;
    long long Krem1, Krem2;
    int d1 = pick_digit(g_hist[0], K, Krem1);
    int d2 = pick_digit(g_hist[1], Krem1, Krem2);
    unsigned long long pref = (((unsigned long long)d1) << 11) | (unsigned)d2;

    int t = blockIdx.x * 256 + threadIdx.x;
    int stride = gridDim.x * 256;
    for (int r = t; r < ROWS_; r += stride) {
        unsigned long long key = g_keys[r];
        if ((key >> 42) == pref) {
            int pos = atomicAdd(&g_cand_cnt, 1);
            if (pos < CAND_CAP) g_cand[pos] = key;
        }
    }
}

// ---------------- K5: exact threshold over remaining 42 bits -----------------
__global__ void __launch_bounds__(256) k_finalsel() {
    long long K = 3LL * g_num_pos;
    if (K > ROWS_) K = ROWS_;
    if (K == 0) { if (threadIdx.x == 0) g_tkey = ~0ull; return; }
    long long Krem1, Krem;
    int d1 = pick_digit(g_hist[0], K, Krem1);
    int d2 = pick_digit(g_hist[1], Krem1, Krem);
    unsigned long long F = (((unsigned long long)d1) << 11) | (unsigned)d2;

    __shared__ int scnt;
    int cnt = g_cand_cnt;
    if (cnt > CAND_CAP) cnt = CAND_CAP;
    for (int b = 41; b >= 0; b--) {
        if (threadIdx.x == 0) scnt = 0;
        __syncthreads();
        int local = 0;
        for (int i = threadIdx.x; i < cnt; i += 256) {
            unsigned long long k2 = g_cand[i];
            if ((k2 >> (b + 1)) == F && ((k2 >> b) & 1ull)) local++;
        }
        if (local) atomicAdd(&scnt, local);
        __syncthreads();
        long long c1 = scnt;
        if (c1 >= Krem) F = (F << 1) | 1ull;
        else { Krem -= c1; F <<= 1; }
        __syncthreads();
    }
    if (threadIdx.x == 0) g_tkey = F;
}

// ---------------- K6: fused keep + CE + output -------------------------------
__global__ void __launch_bounds__(256)
k_ce(const float* __restrict__ conf_data, float* __restrict__ out) {
    const float NINF = __int_as_float(0xff800000);
    long long K = 3LL * g_num_pos;
    if (K > ROWS_) K = ROWS_;
    unsigned long long tkey = g_tkey;

    const int lane = threadIdx.x & 31;
    const int wid  = (blockIdx.x * blockDim.x + threadIdx.x) >> 5;
    const int nw   = (gridDim.x * blockDim.x) >> 5;
    const int NG = ROWS_ / 32;

    float lce = 0.f;
    int   lkp = 0;

    for (int g32 = wid; g32 < NG; g32 += nw) {
        int r = g32 * 32 + lane;
        int c = g_conf[r];
        bool keep = (c > 0) || (c == 0 && K > 0 && g_keys[r] >= tkey);
        unsigned bal = __ballot_sync(0xffffffffu, keep);
        lkp += (lane == 0) ? __popc(bal) : 0;
        while (bal) {
            int bit = __ffs(bal) - 1;
            bal &= bal - 1;
            int rk = g32 * 32 + bit;
            int cw = __shfl_sync(0xffffffffu, c, bit);
            int ct = cw > 0 ? cw : 0;
            const float* row = conf_data + (size_t)rk * C_;
            float x0 = row[lane];
            float x1 = row[lane + 32];
            float x2 = (lane < 17) ? row[lane + 64] : NINF;
            float m = fmaxf(x0, fmaxf(x1, x2));
            #pragma unroll
            for (int o = 16; o; o >>= 1)
                m = fmaxf(m, __shfl_xor_sync(0xffffffffu, m, o));
            float s = expf(x0 - m) + expf(x1 - m) +
                      ((lane < 17) ? expf(x2 - m) : 0.f);
            #pragma unroll
            for (int o = 16; o; o >>= 1) s += __shfl_xor_sync(0xffffffffu, s, o);
            float tv = NINF;
            if (lane == ct)                   tv = x0;
            if (lane + 32 == ct)              tv = x1;
            if (lane < 17 && lane + 64 == ct) tv = x2;
            #pragma unroll
            for (int o = 16; o; o >>= 1)
                tv = fmaxf(tv, __shfl_xor_sync(0xffffffffu, tv, o));
            if (lane == 0) lce += (m + logf(s)) - tv;
        }
    }

    __shared__ float sf[8];
    __shared__ int   si[8];
    int w = threadIdx.x >> 5;
    if (lane == 0) { sf[w] = lce; si[w] = lkp; }
    __syncthreads();
    if (threadIdx.x == 0) {
        float a = 0.f; int k = 0;
        #pragma unroll
        for (int i = 0; i < 8; i++) { a += sf[i]; k += si[i]; }
        if (k)        atomicAdd(&g_keep, k);
        if (a != 0.f) atomicAdd(&g_ce_sum, a);
        __threadfence();
        int done = atomicAdd(&g_done, 1);
        if (done == (int)gridDim.x - 1) {
            int np = g_num_pos; if (np < 1) np = 1;
            int kp = g_keep;    if (kp < 1) kp = 1;
            out[0] = g_sl1    / (float)np;
            out[1] = g_ce_sum / (float)kp;
        }
    }
}

// ---------------- host -------------------------------------------------------
extern "C" void kernel_launch(void* const* d_in, const int* in_sizes, int n_in,
                              void* d_out, int out_size) {
    const float* loc = nullptr;
    const float* conf = nullptr;
    const float* priors = nullptr;
    const float* gtb = nullptr;
    const int*   gtl = nullptr;
    for (int i = 0; i < n_in; i++) {
        long long s = in_sizes[i];
        if      (s == (long long)B_ * P_ * C_) conf   = (const float*)d_in[i];
        else if (s == (long long)B_ * P_ * 4)  loc    = (const float*)d_in[i];
        else if (s == (long long)P_ * 4)       priors = (const float*)d_in[i];
        else if (s == (long long)B_ * N_ * 4)  gtb    = (const float*)d_in[i];
        else if (s == (long long)B_ * N_)      gtl    = (const int*)d_in[i];
    }
    float* out = (float*)d_out;

    k_init<<<1, 1024>>>();
    k_match<<<dim3((P_ + 255) / 256, B_), 256>>>(priors, gtb);
    k_conf<<<1776, 256>>>(conf, loc, priors, gtb, gtl);
    k_hist2<<<296, 256>>>();
    k_collect<<<296, 256>>>();
    k_finalsel<<<1, 256>>>();
    k_ce<<<1776, 256>>>(conf, out);
}

// round 4
// speedup vs baseline: 1.8998x; 1.0575x over previous
#include <cuda_runtime.h>

#define B_ 8
#define P_ 57744
#define C_ 81
#define N_ 20
#define ROWS_ (B_ * P_)
#define POS_TH 0.5f
#define NEG_TH 0.4f
#define CAND_CAP 65536
#define SM_CAND 6144

// ---------------- scratch (static __device__, no allocation) ----------------
__device__ unsigned char      g_mt[ROWS_];      // (gt_idx<<2) | band
__device__ unsigned long long g_gt_best[B_ * N_];
__device__ unsigned long long g_keys[ROWS_];
__device__ signed char        g_conf[ROWS_];
__device__ int                g_hist[2][2048];
__device__ unsigned long long g_cand[CAND_CAP];
__device__ int                g_cand_cnt;
__device__ unsigned long long g_tkey;
__device__ int                g_num_pos;
__device__ int                g_keep;
__device__ float              g_sl1;
__device__ float              g_ce_sum;
__device__ int                g_done;
__device__ int                g_sel_done;

__device__ __forceinline__ float smooth_l1(float d) {
    float ad = fabsf(d);
    return ad < 1.f ? 0.5f * d * d : ad - 0.5f;
}
__device__ __forceinline__ unsigned ord_bits(float x) {
    unsigned b = __float_as_uint(x);
    unsigned m = (unsigned)((int)b >> 31) | 0x80000000u;
    return b ^ m;   // monotonic float -> uint
}

// block-cooperative: digit of the Krem-th largest key in an 11-bit histogram.
__device__ int pick_digit(const int* hist, long long Krem_in, long long& Krem_out) {
    __shared__ long long part[256];
    __shared__ int s_d;
    __shared__ long long s_krem;
    int t = threadIdx.x;
    long long s = 0;
    #pragma unroll
    for (int i = 0; i < 8; i++) s += hist[t * 8 + i];
    part[t] = s;
    __syncthreads();
    if (t == 0) {
        long long above = 0;
        int seg = 255;
        for (; seg > 0; seg--) {
            if (above + part[seg] >= Krem_in) break;
            above += part[seg];
        }
        int d = seg * 8;
        for (int i = 7; i >= 0; i--) {
            int cgt = hist[seg * 8 + i];
            if (above + cgt >= Krem_in) { d = seg * 8 + i; break; }
            above += cgt;
        }
        s_d = d;
        s_krem = Krem_in - above;
    }
    __syncthreads();
    Krem_out = s_krem;
    return s_d;
}

// ---------------- K0: per-replay reset ---------------------------------------
__global__ void k_init() {
    int t = threadIdx.x;
    if (t == 0) {
        g_num_pos = 0; g_sl1 = 0.f; g_ce_sum = 0.f;
        g_keep = 0; g_cand_cnt = 0; g_done = 0; g_sel_done = 0;
    }
    for (int i = t; i < 2 * 2048; i += blockDim.x) (&g_hist[0][0])[i] = 0;
    if (t < B_ * N_) g_gt_best[t] = 0x00000000FFFFFFFFull;  // fallback prior 0
}

// ---------------- K1: matching (writes 1B/row band+idx) ----------------------
__global__ void k_match(const float* __restrict__ priors,
                        const float* __restrict__ gt_boxes) {
    int b = blockIdx.y;
    int p = blockIdx.x * 256 + threadIdx.x;

    __shared__ float4 s_gt[N_];
    __shared__ float  s_area[N_];
    __shared__ unsigned long long s_best[N_];
    if (threadIdx.x < N_) {
        float4 g = reinterpret_cast<const float4*>(gt_boxes)[b * N_ + threadIdx.x];
        s_gt[threadIdx.x] = g;
        s_area[threadIdx.x] = (g.z - g.x) * (g.w - g.y);
        s_best[threadIdx.x] = 0ull;
    }
    __syncthreads();

    if (p < P_) {
        float4 pr = reinterpret_cast<const float4*>(priors)[p];
        float px1 = pr.x - pr.z * 0.5f, py1 = pr.y - pr.w * 0.5f;
        float px2 = pr.x + pr.z * 0.5f, py2 = pr.y + pr.w * 0.5f;
        float parea = (px2 - px1) * (py2 - py1);

        float best = 0.f; int bestn = 0;
        #pragma unroll
        for (int n = 0; n < N_; n++) {
            float4 g = s_gt[n];
            float ix1 = fmaxf(px1, g.x), iy1 = fmaxf(py1, g.y);
            float ix2 = fminf(px2, g.z), iy2 = fminf(py2, g.w);
            float iw = fmaxf(ix2 - ix1, 0.f), ih = fmaxf(iy2 - iy1, 0.f);
            float inter = iw * ih;
            float iou = inter / (s_area[n] + parea - inter);
            if (iou > best) { best = iou; bestn = n; }
            if (inter > 0.f) {
                unsigned long long key =
                    (((unsigned long long)__float_as_uint(iou)) << 32) |
                    (unsigned)(~(unsigned)p);
                atomicMax(&s_best[n], key);
            }
        }
        int band = (best < NEG_TH) ? 0 : ((best < POS_TH) ? 1 : 2);
        g_mt[b * P_ + p] = (unsigned char)((bestn << 2) | band);
    }
    __syncthreads();
    if (threadIdx.x < N_)
        atomicMax(&g_gt_best[b * N_ + threadIdx.x], s_best[threadIdx.x]);
}

// ---------------- K2: conf scan + force-match + loc loss + round-1 hist ------
__global__ void __launch_bounds__(256)
k_conf(const float* __restrict__ conf_data,
       const float* __restrict__ loc_data,
       const float* __restrict__ priors,
       const float* __restrict__ gt_boxes,
       const int* __restrict__ gt_labels) {
    const float NINF = __int_as_float(0xff800000);
    __shared__ int s_hist[2048];
    __shared__ int s_forced[B_ * N_];
    __shared__ int s_labels[B_ * N_];
    for (int i = threadIdx.x; i < 2048; i += 256) s_hist[i] = 0;
    if (threadIdx.x < B_ * N_) {
        s_forced[threadIdx.x] =
            (int)(~(unsigned)(g_gt_best[threadIdx.x] & 0xFFFFFFFFull));
        s_labels[threadIdx.x] = gt_labels[threadIdx.x];
    }
    __syncthreads();

    const int lane = threadIdx.x & 31;
    const int wid  = (blockIdx.x * blockDim.x + threadIdx.x) >> 5;
    const int nw   = (gridDim.x * blockDim.x) >> 5;

    float lsl = 0.f;
    int   lnp = 0;
    const int NCH = ROWS_ / 8;

    for (int ch = wid; ch < NCH; ch += nw) {
        int r0 = ch * 8;
        const float* base = conf_data + (size_t)r0 * C_;
        float xa[8], xb[8], xc[8];
        #pragma unroll
        for (int j = 0; j < 8; j++) {
            const float* row = base + j * C_;
            xa[j] = __ldcs(row + lane);
            xb[j] = __ldcs(row + lane + 32);
            xc[j] = (lane < 17) ? __ldcs(row + lane + 64) : NINF;
        }
        unsigned mr[8];
        #pragma unroll
        for (int j = 0; j < 8; j++) {
            float f = fmaxf(fmaxf(lane ? xa[j] : NINF, xb[j]),
                            (lane < 17) ? xc[j] : NINF);
            mr[j] = __reduce_max_sync(0xffffffffu, ord_bits(f));
        }
        if (lane < 8) {
            unsigned uu = (lane & 4)
                ? ((lane & 2) ? ((lane & 1) ? mr[7] : mr[6])
                              : ((lane & 1) ? mr[5] : mr[4]))
                : ((lane & 2) ? ((lane & 1) ? mr[3] : mr[2])
                              : ((lane & 1) ? mr[1] : mr[0]));
            int r = r0 + lane;
            int b = r / P_;
            int p = r - b * P_;
            unsigned mt = g_mt[r];
            int band = mt & 3;
            int n = mt >> 2;
            #pragma unroll
            for (int n2 = 0; n2 < N_; n2++)
                if (s_forced[b * N_ + n2] == p) { band = 2; n = n2; }
            int c = (band == 0) ? 0 : ((band == 1) ? -1 : s_labels[b * N_ + n]);
            g_conf[r] = (signed char)c;
            unsigned u = (c == 0) ? uu : 0u;
            unsigned long long key =
                (((unsigned long long)u) << 32) | (unsigned)(~(unsigned)r);
            g_keys[r] = key;
            atomicAdd(&s_hist[(int)(key >> 53)], 1);
            if (c > 0) {
                lnp++;
                float4 pr = reinterpret_cast<const float4*>(priors)[p];
                float4 g  = reinterpret_cast<const float4*>(gt_boxes)[b * N_ + n];
                float4 ld = reinterpret_cast<const float4*>(loc_data)[r];
                float tx = ((g.x + g.z) * 0.5f - pr.x) / (0.1f * pr.z);
                float ty = ((g.y + g.w) * 0.5f - pr.y) / (0.1f * pr.w);
                float tw = logf((g.z - g.x) / pr.z) * 5.0f;
                float th = logf((g.w - g.y) / pr.w) * 5.0f;
                lsl += smooth_l1(ld.x - tx) + smooth_l1(ld.y - ty)
                     + smooth_l1(ld.z - tw) + smooth_l1(ld.w - th);
            }
        }
    }

    #pragma unroll
    for (int o = 16; o; o >>= 1) {
        lsl += __shfl_xor_sync(0xffffffffu, lsl, o);
        lnp += __shfl_xor_sync(0xffffffffu, lnp, o);
    }
    __shared__ float sf[8];
    __shared__ int   si[8];
    int w = threadIdx.x >> 5;
    if (lane == 0) { sf[w] = lsl; si[w] = lnp; }
    __syncthreads();
    if (threadIdx.x == 0) {
        float a = 0.f; int ni = 0;
        #pragma unroll
        for (int i = 0; i < 8; i++) { a += sf[i]; ni += si[i]; }
        if (ni)       atomicAdd(&g_num_pos, ni);
        if (a != 0.f) atomicAdd(&g_sl1, a);
    }
    __syncthreads();
    for (int i = threadIdx.x; i < 2048; i += 256) {
        int v = s_hist[i];
        if (v) atomicAdd(&g_hist[0][i], v);
    }
}

// ---------------- K3: round-2 histogram (vectorized key scan) ----------------
__global__ void __launch_bounds__(256) k_hist2() {
    long long K = 3LL * g_num_pos;
    if (K > ROWS_) K = ROWS_;
    if (K == 0) return;
    long long Krem;
    int d1 = pick_digit(g_hist[0], K, Krem);
    unsigned long long pref = (unsigned long long)d1;

    __shared__ int sh[2048];
    for (int i = threadIdx.x; i < 2048; i += 256) sh[i] = 0;
    __syncthreads();
    const ulonglong2* kp = reinterpret_cast<const ulonglong2*>(g_keys);
    int t = blockIdx.x * 256 + threadIdx.x;
    int stride = gridDim.x * 256;
    for (int i = t; i < ROWS_ / 2; i += stride) {
        ulonglong2 kk = kp[i];
        if ((kk.x >> 53) == pref) atomicAdd(&sh[(int)((kk.x >> 42) & 2047)], 1);
        if ((kk.y >> 53) == pref) atomicAdd(&sh[(int)((kk.y >> 42) & 2047)], 1);
    }
    __syncthreads();
    for (int i = threadIdx.x; i < 2048; i += 256) {
        int v = sh[i];
        if (v) atomicAdd(&g_hist[1][i], v);
    }
}

// ---------------- K4: collect ties + (last block) exact 42-bit resolve -------
__global__ void __launch_bounds__(256) k_collect_sel() {
    long long K = 3LL * g_num_pos;
    if (K > ROWS_) K = ROWS_;
    if (K == 0) { if (blockIdx.x == 0 && threadIdx.x == 0) g_tkey = ~0ull; return; }
    long long Krem1, Krem;
    int d1 = pick_digit(g_hist[0], K, Krem1);
    int d2 = pick_digit(g_hist[1], Krem1, Krem);
    unsigned long long pref = (((unsigned long long)d1) << 11) | (unsigned)d2;

    const ulonglong2* kp = reinterpret_cast<const ulonglong2*>(g_keys);
    int t = blockIdx.x * 256 + threadIdx.x;
    int stride = gridDim.x * 256;
    for (int i = t; i < ROWS_ / 2; i += stride) {
        ulonglong2 kk = kp[i];
        if ((kk.x >> 42) == pref) {
            int pos = atomicAdd(&g_cand_cnt, 1);
            if (pos < CAND_CAP) g_cand[pos] = kk.x;
        }
        if ((kk.y >> 42) == pref) {
            int pos = atomicAdd(&g_cand_cnt, 1);
            if (pos < CAND_CAP) g_cand[pos] = kk.y;
        }
    }

    // last block resolves the final threshold exactly
    __shared__ int s_last;
    __shared__ int scnt;
    __shared__ unsigned long long s_cand[SM_CAND];
    __threadfence();
    if (threadIdx.x == 0)
        s_last = (atomicAdd(&g_sel_done, 1) == (int)gridDim.x - 1);
    __syncthreads();
    if (!s_last) return;

    int cnt = g_cand_cnt;
    if (cnt > CAND_CAP) cnt = CAND_CAP;
    bool in_sm = (cnt <= SM_CAND);
    if (in_sm)
        for (int i = threadIdx.x; i < cnt; i += 256) s_cand[i] = g_cand[i];
    __syncthreads();

    unsigned long long F = pref;
    for (int b = 41; b >= 0; b--) {
        if (threadIdx.x == 0) scnt = 0;
        __syncthreads();
        int local = 0;
        for (int i = threadIdx.x; i < cnt; i += 256) {
            unsigned long long k2 = in_sm ? s_cand[i] : g_cand[i];
            if ((k2 >> (b + 1)) == F && ((k2 >> b) & 1ull)) local++;
        }
        if (local) atomicAdd(&scnt, local);
        __syncthreads();
        long long c1 = scnt;
        if (c1 >= Krem) F = (F << 1) | 1ull;
        else { Krem -= c1; F <<= 1; }
        __syncthreads();
    }
    if (threadIdx.x == 0) g_tkey = F;
}

// ---------------- K5: fused keep + CE + output -------------------------------
__global__ void __launch_bounds__(256)
k_ce(const float* __restrict__ conf_data, float* __restrict__ out) {
    const float NINF = __int_as_float(0xff800000);
    long long K = 3LL * g_num_pos;
    if (K > ROWS_) K = ROWS_;
    unsigned long long tkey = g_tkey;

    const int lane = threadIdx.x & 31;
    const int wid  = (blockIdx.x * blockDim.x + threadIdx.x) >> 5;
    const int nw   = (gridDim.x * blockDim.x) >> 5;
    const int NG = ROWS_ / 32;

    float lce = 0.f;
    int   lkp = 0;

    for (int g32 = wid; g32 < NG; g32 += nw) {
        int r = g32 * 32 + lane;
        int c = g_conf[r];
        bool keep = (c > 0) || (c == 0 && K > 0 && g_keys[r] >= tkey);
        unsigned bal = __ballot_sync(0xffffffffu, keep);
        lkp += (lane == 0) ? __popc(bal) : 0;
        while (bal) {
            int bit = __ffs(bal) - 1;
            bal &= bal - 1;
            int rk = g32 * 32 + bit;
            int cw = __shfl_sync(0xffffffffu, c, bit);
            int ct = cw > 0 ? cw : 0;
            const float* row = conf_data + (size_t)rk * C_;
            float x0 = row[lane];
            float x1 = row[lane + 32];
            float x2 = (lane < 17) ? row[lane + 64] : NINF;
            float m = fmaxf(x0, fmaxf(x1, x2));
            #pragma unroll
            for (int o = 16; o; o >>= 1)
                m = fmaxf(m, __shfl_xor_sync(0xffffffffu, m, o));
            float s = expf(x0 - m) + expf(x1 - m) +
                      ((lane < 17) ? expf(x2 - m) : 0.f);
            #pragma unroll
            for (int o = 16; o; o >>= 1) s += __shfl_xor_sync(0xffffffffu, s, o);
            float tv = NINF;
            if (lane == ct)                   tv = x0;
            if (lane + 32 == ct)              tv = x1;
            if (lane < 17 && lane + 64 == ct) tv = x2;
            #pragma unroll
            for (int o = 16; o; o >>= 1)
                tv = fmaxf(tv, __shfl_xor_sync(0xffffffffu, tv, o));
            if (lane == 0) lce += (m + logf(s)) - tv;
        }
    }

    __shared__ float sf[8];
    __shared__ int   si[8];
    int w = threadIdx.x >> 5;
    if (lane == 0) { sf[w] = lce; si[w] = lkp; }
    __syncthreads();
    if (threadIdx.x == 0) {
        float a = 0.f; int k = 0;
        #pragma unroll
        for (int i = 0; i < 8; i++) { a += sf[i]; k += si[i]; }
        if (k)        atomicAdd(&g_keep, k);
        if (a != 0.f) atomicAdd(&g_ce_sum, a);
        __threadfence();
        int done = atomicAdd(&g_done, 1);
        if (done == (int)gridDim.x - 1) {
            int np = g_num_pos; if (np < 1) np = 1;
            int kp = g_keep;    if (kp < 1) kp = 1;
            out[0] = g_sl1    / (float)np;
            out[1] = g_ce_sum / (float)kp;
        }
    }
}

// ---------------- host -------------------------------------------------------
extern "C" void kernel_launch(void* const* d_in, const int* in_sizes, int n_in,
                              void* d_out, int out_size) {
    const float* loc = nullptr;
    const float* conf = nullptr;
    const float* priors = nullptr;
    const float* gtb = nullptr;
    const int*   gtl = nullptr;
    for (int i = 0; i < n_in; i++) {
        long long s = in_sizes[i];
        if      (s == (long long)B_ * P_ * C_) conf   = (const float*)d_in[i];
        else if (s == (long long)B_ * P_ * 4)  loc    = (const float*)d_in[i];
        else if (s == (long long)P_ * 4)       priors = (const float*)d_in[i];
        else if (s == (long long)B_ * N_ * 4)  gtb    = (const float*)d_in[i];
        else if (s == (long long)B_ * N_)      gtl    = (const int*)d_in[i];
    }
    float* out = (float*)d_out;

    k_init<<<1, 1024>>>();
    k_match<<<dim3((P_ + 255) / 256, B_), 256>>>(priors, gtb);
    k_conf<<<1776, 256>>>(conf, loc, priors, gtb, gtl);
    k_hist2<<<888, 256>>>();
    k_collect_sel<<<888, 256>>>();
    k_ce<<<1776, 256>>>(conf, out);
}